// round 1
// baseline (speedup 1.0000x reference)
#include <cuda_runtime.h>
#include <cuda_bf16.h>
#include <math.h>

#define B     64
#define T     256
#define DIM   1024
#define EMB   256
#define VOCAB 256
#define G4    4096   // 4*DIM

#define LOGITS_N (B*T*VOCAB)     // 4194304
#define HC_N     (2*B*DIM)       // 131072

// ---------------- device scratch (allocation-free rule: __device__ globals) ---
__device__ float g_Wih0[G4*EMB];        //  4 MB
__device__ float g_Whh0[G4*DIM];        // 16.8 MB
__device__ float g_xg  [(size_t)T*B*G4];// 268 MB (reused by both layers)
__device__ float g_hs0 [(size_t)T*B*DIM]; // 67 MB, layout [t][b][d]
__device__ float g_hs1 [(size_t)T*B*DIM]; // 67 MB
__device__ float g_cbuf[2][2][B*DIM];   // [layer][parity]

// ---------------- weight norm ------------------------------------------------
// mode 0: v_ih0 (K=256) -> g_Wih0 ; mode 1: v_hh0 (K=1024) -> g_Whh0
__global__ void wnorm_kernel(const float* __restrict__ v,
                             const float* __restrict__ g, int mode)
{
    const int K = mode ? DIM : EMB;
    float* W = mode ? g_Whh0 : g_Wih0;
    int row = blockIdx.x;
    __shared__ float red[256];
    float s = 0.f;
    for (int i = threadIdx.x; i < K; i += 256) {
        float x = v[(size_t)row*K + i];
        s += x*x;
    }
    red[threadIdx.x] = s;
    __syncthreads();
    for (int o = 128; o > 0; o >>= 1) {
        if (threadIdx.x < o) red[threadIdx.x] += red[threadIdx.x + o];
        __syncthreads();
    }
    float scale = g[row] / sqrtf(red[0]);
    for (int i = threadIdx.x; i < K; i += 256)
        W[(size_t)row*K + i] = v[(size_t)row*K + i] * scale;
}

// ---------------- init c buffers --------------------------------------------
__global__ void init_c_kernel(const float* __restrict__ c0)
{
    int i = blockIdx.x*blockDim.x + threadIdx.x;
    if (i < HC_N) {
        int l = i / (B*DIM);
        g_cbuf[l][0][i % (B*DIM)] = c0[i];
    }
}

// ---------------- generic 128x128x8 fp32 GEMM: C = A * B^T + bias -----------
// A rows are M=(t*64+b). mode 0: A = emb gathered via x, C = g_xg
//                        mode 1: A = g_hs0,               C = g_xg
//                        mode 2: A = g_hs1,               C = d_out (remap b,t,v)
__global__ __launch_bounds__(256, 2)
void gemm128_kernel(int mode,
                    const float* __restrict__ Aext,
                    const float* __restrict__ Bext,
                    float* __restrict__ Cext,
                    const float* __restrict__ bias1,
                    const float* __restrict__ bias2,
                    const int* __restrict__ xidx,
                    int N, int K)
{
    const float* A  = (mode == 0) ? Aext : (mode == 1 ? g_hs0 : g_hs1);
    const float* Bm = (mode == 0) ? g_Wih0 : Bext;
    float* C        = (mode == 2) ? Cext : g_xg;

    __shared__ float As[8][128];
    __shared__ float Bs[8][128];

    int tid = threadIdx.x;
    int tx = tid & 15, ty = tid >> 4;
    int m0 = blockIdx.y * 128, n0 = blockIdx.x * 128;

    int lrow = tid >> 1;
    int kq   = (tid & 1) * 4;

    int m = m0 + lrow;
    const float* arow;
    if (mode == 0) {
        int b = m & 63, t = m >> 6;
        arow = A + (size_t)xidx[b*T + t] * K;
    } else {
        arow = A + (size_t)m * K;
    }
    const float* brow = Bm + (size_t)(n0 + lrow) * K;

    float acc[8][8];
#pragma unroll
    for (int i = 0; i < 8; i++)
#pragma unroll
        for (int j = 0; j < 8; j++) acc[i][j] = 0.f;

    for (int kc = 0; kc < K; kc += 8) {
        float4 av = *(const float4*)(arow + kc + kq);
        float4 bv = *(const float4*)(brow + kc + kq);
        __syncthreads();
        As[kq+0][lrow] = av.x; As[kq+1][lrow] = av.y;
        As[kq+2][lrow] = av.z; As[kq+3][lrow] = av.w;
        Bs[kq+0][lrow] = bv.x; Bs[kq+1][lrow] = bv.y;
        Bs[kq+2][lrow] = bv.z; Bs[kq+3][lrow] = bv.w;
        __syncthreads();
#pragma unroll
        for (int k = 0; k < 8; k++) {
            float a[8], bb[8];
            *(float4*)&a[0]  = *(const float4*)&As[k][ty*8];
            *(float4*)&a[4]  = *(const float4*)&As[k][ty*8 + 4];
            *(float4*)&bb[0] = *(const float4*)&Bs[k][tx*8];
            *(float4*)&bb[4] = *(const float4*)&Bs[k][tx*8 + 4];
#pragma unroll
            for (int i = 0; i < 8; i++)
#pragma unroll
                for (int j = 0; j < 8; j++)
                    acc[i][j] += a[i] * bb[j];
        }
    }

#pragma unroll
    for (int i = 0; i < 8; i++) {
        int mm = m0 + ty*8 + i;
#pragma unroll
        for (int j = 0; j < 8; j++) {
            int nn = n0 + tx*8 + j;
            float v = acc[i][j] + bias1[nn] + (bias2 ? bias2[nn] : 0.f);
            if (mode == 2) {
                int b = mm & 63, t = mm >> 6;
                C[(size_t)b*(T*VOCAB) + (size_t)t*VOCAB + nn] = v;
            } else {
                C[(size_t)mm*N + nn] = v;
            }
        }
    }
}

// ---------------- fused LSTM step: gates = xg_t + h @ Whh^T; activations ----
// grid (128 d-groups of 8, 2 b-groups of 32), 128 threads.
// thread: 2 b x 1 d x 4 gates = 8 accumulators, K tiled by 64 in smem.
__global__ __launch_bounds__(128)
void lstm_step_kernel(int t, int layer,
                      const float* __restrict__ h0,       // [2][B][DIM]
                      const float* __restrict__ Whh_ext)  // W_hh1 for layer 1
{
    const float* Whh = layer ? Whh_ext : g_Whh0;
    float* hs        = layer ? g_hs1 : g_hs0;
    const float* h_prev = (t == 0) ? (h0 + (size_t)layer*B*DIM)
                                   : (hs + (size_t)(t-1)*B*DIM);
    float* h_out     = hs + (size_t)t*B*DIM;
    const float* xg_t = g_xg + (size_t)t*B*G4;
    const float* c_in = g_cbuf[layer][t & 1];
    float*       c_out = g_cbuf[layer][(t+1) & 1];

    __shared__ float h_s[32][68];
    __shared__ float w_s[32][68];

    int tid = threadIdx.x;
    int d  = tid & 7;
    int bq = tid >> 3;           // 0..15
    int d8  = blockIdx.x * 8;
    int b32 = blockIdx.y * 32;

    float acc[2][4];
#pragma unroll
    for (int j = 0; j < 2; j++)
#pragma unroll
        for (int gg = 0; gg < 4; gg++) acc[j][gg] = 0.f;

    for (int kc = 0; kc < DIM; kc += 64) {
        __syncthreads();
#pragma unroll
        for (int i = 0; i < 4; i++) {
            int idx  = tid + i*128;
            int row  = idx >> 4;       // 0..31
            int colq = idx & 15;       // 0..15 -> col = colq*4
            float4 hv = *(const float4*)(h_prev + (size_t)(b32+row)*DIM + kc + colq*4);
            *(float4*)&h_s[row][colq*4] = hv;
            int grow = (row >> 3)*DIM + d8 + (row & 7);   // gate*1024 + d8 + d
            float4 wv = *(const float4*)(Whh + (size_t)grow*DIM + kc + colq*4);
            *(float4*)&w_s[row][colq*4] = wv;
        }
        __syncthreads();
#pragma unroll
        for (int k4 = 0; k4 < 16; k4++) {
            float4 hv0 = *(const float4*)&h_s[bq*2 + 0][k4*4];
            float4 hv1 = *(const float4*)&h_s[bq*2 + 1][k4*4];
#pragma unroll
            for (int gg = 0; gg < 4; gg++) {
                float4 wv = *(const float4*)&w_s[gg*8 + d][k4*4];
                acc[0][gg] += hv0.x*wv.x + hv0.y*wv.y + hv0.z*wv.z + hv0.w*wv.w;
                acc[1][gg] += hv1.x*wv.x + hv1.y*wv.y + hv1.z*wv.z + hv1.w*wv.w;
            }
        }
    }

#pragma unroll
    for (int j = 0; j < 2; j++) {
        int b  = b32 + bq*2 + j;
        int dg = d8 + d;
        size_t base = (size_t)b*G4 + dg;
        float gi = acc[j][0] + xg_t[base];
        float gf = acc[j][1] + xg_t[base + 1024];
        float gc = acc[j][2] + xg_t[base + 2048];
        float go = acc[j][3] + xg_t[base + 3072];
        float si = 1.f / (1.f + expf(-gi));
        float sf = 1.f / (1.f + expf(-gf));
        float so = 1.f / (1.f + expf(-go));
        float cv = sf * c_in[(size_t)b*DIM + dg] + si * tanhf(gc);
        float hv = so * tanhf(cv);
        c_out[(size_t)b*DIM + dg] = cv;
        h_out[(size_t)b*DIM + dg] = hv;
    }
}

// ---------------- pack new_h / new_c into d_out tail ------------------------
__global__ void finals_kernel(float* __restrict__ out)
{
    int i = blockIdx.x*blockDim.x + threadIdx.x;
    if (i < HC_N) {
        int l = i / (B*DIM);
        int r = i % (B*DIM);
        const float* hsl = l ? g_hs1 : g_hs0;
        out[LOGITS_N + i]        = hsl[(size_t)(T-1)*B*DIM + r];
        out[LOGITS_N + HC_N + i] = g_cbuf[l][0][r];   // final parity = (255+1)&1 = 0
    }
}

// ---------------- launch -----------------------------------------------------
extern "C" void kernel_launch(void* const* d_in, const int* in_sizes, int n_in,
                              void* d_out, int out_size)
{
    const int*   x     = (const int*)  d_in[0];
    const float* h0    = (const float*)d_in[1];
    const float* c0    = (const float*)d_in[2];
    const float* emb   = (const float*)d_in[3];
    const float* v_ih0 = (const float*)d_in[4];
    const float* g_ih0 = (const float*)d_in[5];
    const float* v_hh0 = (const float*)d_in[6];
    const float* g_hh0 = (const float*)d_in[7];
    const float* b_ih0 = (const float*)d_in[8];
    const float* b_hh0 = (const float*)d_in[9];
    const float* W_ih1 = (const float*)d_in[10];
    const float* W_hh1 = (const float*)d_in[11];
    const float* b_ih1 = (const float*)d_in[12];
    const float* b_hh1 = (const float*)d_in[13];
    const float* W_out = (const float*)d_in[14];
    const float* b_out = (const float*)d_in[15];
    float* out = (float*)d_out;

    // weight-norm both layer-0 weight matrices
    wnorm_kernel<<<G4, 256>>>(v_ih0, g_ih0, 0);
    wnorm_kernel<<<G4, 256>>>(v_hh0, g_hh0, 1);
    init_c_kernel<<<(HC_N + 255)/256, 256>>>(c0);

    // layer 0 input-side gates: xg = emb[x] @ Wih0^T + b_ih0 + b_hh0
    gemm128_kernel<<<dim3(G4/128, (T*B)/128), 256>>>(
        0, emb, nullptr, nullptr, b_ih0, b_hh0, x, G4, EMB);

    // layer 0 recurrence
    for (int t = 0; t < T; t++)
        lstm_step_kernel<<<dim3(DIM/8, 2), 128>>>(t, 0, h0, nullptr);

    // layer 1 input-side gates: xg = h1s @ Wih1^T + b_ih1 + b_hh1
    gemm128_kernel<<<dim3(G4/128, (T*B)/128), 256>>>(
        1, nullptr, W_ih1, nullptr, b_ih1, b_hh1, nullptr, G4, DIM);

    // layer 1 recurrence
    for (int t = 0; t < T; t++)
        lstm_step_kernel<<<dim3(DIM/8, 2), 128>>>(t, 1, h0, W_hh1);

    // logits = h2s @ W_out^T + b_out  (remapped to [b][t][v])
    gemm128_kernel<<<dim3(VOCAB/128, (T*B)/128), 256>>>(
        2, nullptr, W_out, out, b_out, nullptr, nullptr, VOCAB, DIM);

    // new_h, new_c
    finals_kernel<<<(HC_N + 255)/256, 256>>>(out);
}

// round 9
// speedup vs baseline: 2.1884x; 2.1884x over previous
#include <cuda_runtime.h>
#include <math.h>

#define B     64
#define T     256
#define DIM   1024
#define EMB   256
#define VOCAB 256
#define G4    4096   // 4*DIM
#define NCTA  128
#define NTHR  128

#define LOGITS_N (B*T*VOCAB)     // 4194304
#define HC_N     (2*B*DIM)       // 131072

// ---------------- device scratch ---------------------------------------------
__device__ float g_Wih0[G4*EMB];          //  4 MB
__device__ float g_Whh0[G4*DIM];          // 16.8 MB
__device__ float g_xg  [(size_t)T*B*G4];  // 268 MB (reused by both layers)
__device__ float g_hs0 [(size_t)T*B*DIM]; // 67 MB, layout [t][b][d]
__device__ float g_hs1 [(size_t)T*B*DIM]; // 67 MB
__device__ float g_cfin[2][B*DIM];
__device__ float g_hex [2][B*DIM];        // tf32-rounded, k-permuted h exchange
__device__ unsigned g_bar_cnt;
__device__ unsigned g_bar_gen;

// ---------------- helpers ----------------------------------------------------
__device__ __forceinline__ unsigned f2tf32(float x){
    unsigned u; asm("cvt.rna.tf32.f32 %0, %1;" : "=r"(u) : "f"(x)); return u;
}
// within each k-octet, store order pairs (k, k+4): pos(i) = i<4 ? 2i : 2(i-4)+1
__device__ __forceinline__ int spf(int i){ return (i < 4) ? 2*i : 2*(i-4)+1; }

__device__ __forceinline__ void mma_tf32(float* c, const unsigned* a, const unsigned* b){
    asm volatile("mma.sync.aligned.m16n8k8.row.col.f32.tf32.tf32.f32 "
        "{%0,%1,%2,%3}, {%4,%5,%6,%7}, {%8,%9}, {%0,%1,%2,%3};\n"
        : "+f"(c[0]), "+f"(c[1]), "+f"(c[2]), "+f"(c[3])
        : "r"(a[0]), "r"(a[1]), "r"(a[2]), "r"(a[3]), "r"(b[0]), "r"(b[1]));
}

__device__ __forceinline__ void grid_barrier(unsigned* bgen){
    __syncthreads();
    if (threadIdx.x == 0){
        __threadfence();                 // release: order this CTA's writes
        unsigned target = ++(*bgen);
        unsigned a = atomicAdd(&g_bar_cnt, 1u);
        if (a == NCTA - 1){
            *(volatile unsigned*)&g_bar_cnt = 0u;
            __threadfence();
            atomicExch(&g_bar_gen, target);
        } else {
            while (*(volatile unsigned*)&g_bar_gen < target) { }
        }
        __threadfence();                 // acquire: order subsequent reads
    }
    __syncthreads();
}

// ---------------- weight norm ------------------------------------------------
__global__ void wnorm_kernel(const float* __restrict__ v,
                             const float* __restrict__ g, int mode)
{
    const int K = mode ? DIM : EMB;
    float* W = mode ? g_Whh0 : g_Wih0;
    int row = blockIdx.x;
    __shared__ float red[256];
    float s = 0.f;
    for (int i = threadIdx.x; i < K; i += 256) {
        float x = v[(size_t)row*K + i];
        s += x*x;
    }
    red[threadIdx.x] = s;
    __syncthreads();
    for (int o = 128; o > 0; o >>= 1) {
        if (threadIdx.x < o) red[threadIdx.x] += red[threadIdx.x + o];
        __syncthreads();
    }
    float scale = g[row] / sqrtf(red[0]);
    for (int i = threadIdx.x; i < K; i += 256)
        W[(size_t)row*K + i] = v[(size_t)row*K + i] * scale;
}

// ---------------- fp32 SIMT GEMM (input-side gates + logits) ----------------
__global__ __launch_bounds__(256, 2)
void gemm128_kernel(int mode,
                    const float* __restrict__ Aext,
                    const float* __restrict__ Bext,
                    float* __restrict__ Cext,
                    const float* __restrict__ bias1,
                    const float* __restrict__ bias2,
                    const int* __restrict__ xidx,
                    int N, int K)
{
    const float* A  = (mode == 0) ? Aext : (mode == 1 ? g_hs0 : g_hs1);
    const float* Bm = (mode == 0) ? g_Wih0 : Bext;
    float* C        = (mode == 2) ? Cext : g_xg;

    __shared__ float As[8][128];
    __shared__ float Bs[8][128];

    int tid = threadIdx.x;
    int tx = tid & 15, ty = tid >> 4;
    int m0 = blockIdx.y * 128, n0 = blockIdx.x * 128;

    int lrow = tid >> 1;
    int kq   = (tid & 1) * 4;

    int m = m0 + lrow;
    const float* arow;
    if (mode == 0) {
        int b = m & 63, t = m >> 6;
        arow = A + (size_t)xidx[b*T + t] * K;
    } else {
        arow = A + (size_t)m * K;
    }
    const float* brow = Bm + (size_t)(n0 + lrow) * K;

    float acc[8][8];
#pragma unroll
    for (int i = 0; i < 8; i++)
#pragma unroll
        for (int j = 0; j < 8; j++) acc[i][j] = 0.f;

    for (int kc = 0; kc < K; kc += 8) {
        float4 av = *(const float4*)(arow + kc + kq);
        float4 bv = *(const float4*)(brow + kc + kq);
        __syncthreads();
        As[kq+0][lrow] = av.x; As[kq+1][lrow] = av.y;
        As[kq+2][lrow] = av.z; As[kq+3][lrow] = av.w;
        Bs[kq+0][lrow] = bv.x; Bs[kq+1][lrow] = bv.y;
        Bs[kq+2][lrow] = bv.z; Bs[kq+3][lrow] = bv.w;
        __syncthreads();
#pragma unroll
        for (int k = 0; k < 8; k++) {
            float a[8], bb[8];
            *(float4*)&a[0]  = *(const float4*)&As[k][ty*8];
            *(float4*)&a[4]  = *(const float4*)&As[k][ty*8 + 4];
            *(float4*)&bb[0] = *(const float4*)&Bs[k][tx*8];
            *(float4*)&bb[4] = *(const float4*)&Bs[k][tx*8 + 4];
#pragma unroll
            for (int i = 0; i < 8; i++)
#pragma unroll
                for (int j = 0; j < 8; j++)
                    acc[i][j] += a[i] * bb[j];
        }
    }

#pragma unroll
    for (int i = 0; i < 8; i++) {
        int mm = m0 + ty*8 + i;
#pragma unroll
        for (int j = 0; j < 8; j++) {
            int nn = n0 + tx*8 + j;
            float v = acc[i][j] + bias1[nn] + (bias2 ? bias2[nn] : 0.f);
            if (mode == 2) {
                int b = mm & 63, t = mm >> 6;
                C[(size_t)b*(T*VOCAB) + (size_t)t*VOCAB + nn] = v;
            } else {
                C[(size_t)mm*N + nn] = v;
            }
        }
    }
}

// ---------------- persistent tf32 mma recurrence kernel ----------------------
// 128 CTAs x 128 threads. CTA j owns dims [8j, 8j+8): 32 gate rows (g*8+dd).
// Per step: D[64,32] = h[64,1024] @ Wslice^T via m16n8k8 tf32 mma,
// activations, write h (full fp32 history + tf32 k-permuted exchange), barrier.
__device__ __forceinline__ void load_chunk(const float* hsrc, int kc, float* Abuf, int tid){
#pragma unroll
    for (int i = 0; i < 8; i++){
        int idx = tid + i*NTHR;          // 0..1023
        int b = idx >> 4, q = idx & 15;
        const float* gp = hsrc + b*DIM + kc*64 + q*4;
        unsigned sa = (unsigned)__cvta_generic_to_shared(Abuf + b*72 + q*4);
        asm volatile("cp.async.cg.shared.global [%0], [%1], 16;\n" :: "r"(sa), "l"(gp));
    }
    asm volatile("cp.async.commit_group;\n");
}

__global__ void __launch_bounds__(NTHR, 1)
lstm_persist_kernel(int layer, const float* __restrict__ h0,
                    const float* __restrict__ c0,
                    const float* __restrict__ Whh_ext)
{
    extern __shared__ float sm[];
    float* W_s = sm;                    // [32][1032] tf32-rounded, k-permuted
    float* A_s = W_s + 32*1032;         // [2][64][72] h chunk double buffer
    float* D_s = A_s + 2*64*72;         // [64][36]
    float* C_s = D_s + 64*36;           // [512] resident cell state

    const int tid  = threadIdx.x;
    const int lane = tid & 31;
    const int warp = tid >> 5;
    const int wy = warp & 1, wx = warp >> 1;   // warp tile m32 x n16
    const int cta = blockIdx.x;
    const int d8  = cta * 8;
    const int m_base = wy*32, n_base = wx*16;

    const float* Whh = layer ? Whh_ext : g_Whh0;
    float* hs = layer ? g_hs1 : g_hs0;
    const float* xg = g_xg;

    unsigned bgen = 0;
    if (tid == 0) bgen = *(volatile unsigned*)&g_bar_gen;

    // one-time: load + permute + tf32-round W slice into smem
    for (int idx = tid; idx < 32*1024; idx += NTHR){
        int n = idx >> 10, k = idx & 1023;
        int g = n >> 3, dd = n & 7;
        float v = Whh[(size_t)(g*1024 + d8 + dd)*DIM + k];
        int kp = (k & ~7) + spf(k & 7);
        W_s[n*1032 + kp] = __uint_as_float(f2tf32(v));
    }
    // init cell state + publish permuted h0
    for (int idx = tid; idx < 512; idx += NTHR){
        int b = idx >> 3, dd = idx & 7;
        C_s[idx] = c0[(size_t)layer*B*DIM + b*DIM + d8 + dd];
        float hv = h0[(size_t)layer*B*DIM + b*DIM + d8 + dd];
        g_hex[0][b*DIM + d8 + spf(dd)] = __uint_as_float(f2tf32(hv));
    }
    grid_barrier(&bgen);

    int p = 0;
    const int j2 = 2*(lane & 3);
    const int arow = lane >> 2;

    for (int t = 0; t < T; t++){
        const float* hsrc = g_hex[p];
        float acc[2][2][4];
#pragma unroll
        for (int mi = 0; mi < 2; mi++)
#pragma unroll
            for (int ni = 0; ni < 2; ni++)
#pragma unroll
                for (int q = 0; q < 4; q++) acc[mi][ni][q] = 0.f;

        load_chunk(hsrc, 0, A_s, tid);

        for (int kc = 0; kc < 16; kc++){
            float* Ab = A_s + (kc & 1)*(64*72);
            if (kc < 15){
                load_chunk(hsrc, kc+1, A_s + ((kc+1)&1)*(64*72), tid);
                asm volatile("cp.async.wait_group 1;\n");
            } else {
                asm volatile("cp.async.wait_group 0;\n");
            }
            __syncthreads();
#pragma unroll
            for (int kk = 0; kk < 8; kk++){
                unsigned a[2][4], bf[2][2];
#pragma unroll
                for (int mi = 0; mi < 2; mi++){
                    const float* ap = Ab + (m_base + mi*16 + arow)*72 + kk*8 + j2;
                    float2 v01 = *(const float2*)ap;            // (a0, a2)
                    float2 v23 = *(const float2*)(ap + 8*72);   // (a1, a3)
                    a[mi][0] = __float_as_uint(v01.x);
                    a[mi][2] = __float_as_uint(v01.y);
                    a[mi][1] = __float_as_uint(v23.x);
                    a[mi][3] = __float_as_uint(v23.y);
                }
#pragma unroll
                for (int ni = 0; ni < 2; ni++){
                    const float* bp = W_s + (n_base + ni*8 + arow)*1032 + kc*64 + kk*8 + j2;
                    float2 bv = *(const float2*)bp;             // (b0, b1)
                    bf[ni][0] = __float_as_uint(bv.x);
                    bf[ni][1] = __float_as_uint(bv.y);
                }
#pragma unroll
                for (int mi = 0; mi < 2; mi++)
#pragma unroll
                    for (int ni = 0; ni < 2; ni++)
                        mma_tf32(acc[mi][ni], a[mi], bf[ni]);
            }
            __syncthreads();
        }

        // dump C fragments to D_s
#pragma unroll
        for (int mi = 0; mi < 2; mi++)
#pragma unroll
            for (int ni = 0; ni < 2; ni++){
                int r = m_base + mi*16 + arow;
                int ccol = n_base + ni*8 + j2;
                D_s[r*36 + ccol]       = acc[mi][ni][0];
                D_s[r*36 + ccol + 1]   = acc[mi][ni][1];
                D_s[(r+8)*36 + ccol]   = acc[mi][ni][2];
                D_s[(r+8)*36 + ccol+1] = acc[mi][ni][3];
            }
        __syncthreads();

        // activations: 512 (b,dd) cells, 4 per thread
#pragma unroll
        for (int ii = 0; ii < 4; ii++){
            int cell = tid + ii*NTHR;
            int b = cell >> 3, dd = cell & 7;
            size_t xb = ((size_t)(t*64 + b))*G4 + d8 + dd;
            float gi = D_s[b*36 + dd]      + xg[xb];
            float gf = D_s[b*36 + 8 + dd]  + xg[xb + 1024];
            float gc = D_s[b*36 + 16 + dd] + xg[xb + 2048];
            float go = D_s[b*36 + 24 + dd] + xg[xb + 3072];
            float si = 1.f/(1.f + expf(-gi));
            float sf = 1.f/(1.f + expf(-gf));
            float so = 1.f/(1.f + expf(-go));
            float cv = sf*C_s[cell] + si*tanhf(gc);
            float hv = so*tanhf(cv);
            C_s[cell] = cv;
            hs[(size_t)t*B*DIM + b*DIM + d8 + dd] = hv;
            g_hex[p^1][b*DIM + d8 + spf(dd)] = __uint_as_float(f2tf32(hv));
        }
        grid_barrier(&bgen);
        p ^= 1;
    }

    // final cell state
    for (int idx = tid; idx < 512; idx += NTHR){
        int b = idx >> 3, dd = idx & 7;
        g_cfin[layer][b*DIM + d8 + dd] = C_s[idx];
    }
}

// ---------------- pack new_h / new_c ----------------------------------------
__global__ void finals_kernel(float* __restrict__ out)
{
    int i = blockIdx.x*blockDim.x + threadIdx.x;
    if (i < HC_N) {
        int l = i / (B*DIM);
        int r = i % (B*DIM);
        const float* hsl = l ? g_hs1 : g_hs0;
        out[LOGITS_N + i]        = hsl[(size_t)(T-1)*B*DIM + r];
        out[LOGITS_N + HC_N + i] = g_cfin[l][r];
    }
}

// ---------------- launch -----------------------------------------------------
#define PERSIST_SMEM ((32*1032 + 2*64*72 + 64*36 + 512) * 4)

extern "C" void kernel_launch(void* const* d_in, const int* in_sizes, int n_in,
                              void* d_out, int out_size)
{
    const int*   x     = (const int*)  d_in[0];
    const float* h0    = (const float*)d_in[1];
    const float* c0    = (const float*)d_in[2];
    const float* emb   = (const float*)d_in[3];
    const float* v_ih0 = (const float*)d_in[4];
    const float* g_ih0 = (const float*)d_in[5];
    const float* v_hh0 = (const float*)d_in[6];
    const float* g_hh0 = (const float*)d_in[7];
    const float* b_ih0 = (const float*)d_in[8];
    const float* b_hh0 = (const float*)d_in[9];
    const float* W_ih1 = (const float*)d_in[10];
    const float* W_hh1 = (const float*)d_in[11];
    const float* b_ih1 = (const float*)d_in[12];
    const float* b_hh1 = (const float*)d_in[13];
    const float* W_out = (const float*)d_in[14];
    const float* b_out = (const float*)d_in[15];
    float* out = (float*)d_out;

    cudaFuncSetAttribute(lstm_persist_kernel,
                         cudaFuncAttributeMaxDynamicSharedMemorySize, PERSIST_SMEM);

    wnorm_kernel<<<G4, 256>>>(v_ih0, g_ih0, 0);
    wnorm_kernel<<<G4, 256>>>(v_hh0, g_hh0, 1);

    // layer 0 input-side gates
    gemm128_kernel<<<dim3(G4/128, (T*B)/128), 256>>>(
        0, emb, nullptr, nullptr, b_ih0, b_hh0, x, G4, EMB);

    // layer 0 recurrence (persistent)
    lstm_persist_kernel<<<NCTA, NTHR, PERSIST_SMEM>>>(0, h0, c0, nullptr);

    // layer 1 input-side gates
    gemm128_kernel<<<dim3(G4/128, (T*B)/128), 256>>>(
        1, nullptr, W_ih1, nullptr, b_ih1, b_hh1, nullptr, G4, DIM);

    // layer 1 recurrence (persistent)
    lstm_persist_kernel<<<NCTA, NTHR, PERSIST_SMEM>>>(1, h0, c0, W_hh1);

    // logits
    gemm128_kernel<<<dim3(VOCAB/128, (T*B)/128), 256>>>(
        2, nullptr, W_out, out, b_out, nullptr, nullptr, VOCAB, DIM);

    finals_kernel<<<(HC_N + 255)/256, 256>>>(out);
}